// round 1
// baseline (speedup 1.0000x reference)
#include <cuda_runtime.h>
#include <cstdint>

#define N_ROWS 16384
#define D 1024
#define BM 128
#define BN 128
#define BK 16
#define TM 8
#define TN 8

typedef unsigned long long ull;

// Scratch (module-static, allowed): normalized features + per-row encoded max dot
__device__ float        g_norm[(size_t)N_ROWS * D];
__device__ unsigned int g_maxenc[N_ROWS];

// Monotonic uint encoding of float (order-preserving for atomicMax)
__device__ __forceinline__ unsigned int enc_f(float f) {
    unsigned int u = __float_as_uint(f);
    return (u & 0x80000000u) ? ~u : (u | 0x80000000u);
}
__device__ __forceinline__ float dec_f(unsigned int e) {
    return (e & 0x80000000u) ? __uint_as_float(e & 0x7FFFFFFFu)
                             : __uint_as_float(~e);
}

__device__ __forceinline__ ull pack2(float lo, float hi) {
    ull r;
    asm("mov.b64 %0, {%1, %2};" : "=l"(r) : "f"(lo), "f"(hi));
    return r;
}
__device__ __forceinline__ void unpack2(float &lo, float &hi, ull v) {
    asm("mov.b64 {%0, %1}, %2;" : "=f"(lo), "=f"(hi) : "l"(v));
}
// Packed f32x2 FMA: d.lo += a.lo*b.lo ; d.hi += a.hi*b.hi
__device__ __forceinline__ void ffma2(ull &d, ull a, ull b) {
    asm("fma.rn.f32x2 %0, %1, %2, %0;" : "+l"(d) : "l"(a), "l"(b));
}

// ---------------------------------------------------------------------------
// Kernel 1: L2-normalize each row; also init the per-row max accumulator.
// One block (256 threads) per row; each thread owns one float4.
// ---------------------------------------------------------------------------
__global__ void normalize_kernel(const float* __restrict__ feats) {
    int row = blockIdx.x;
    const float4* src = reinterpret_cast<const float4*>(feats + (size_t)row * D);
    float4 f = src[threadIdx.x];
    float ss = f.x * f.x + f.y * f.y + f.z * f.z + f.w * f.w;
    #pragma unroll
    for (int o = 16; o; o >>= 1) ss += __shfl_xor_sync(0xffffffffu, ss, o);
    __shared__ float warpsum[8];
    if ((threadIdx.x & 31) == 0) warpsum[threadIdx.x >> 5] = ss;
    __syncthreads();
    if (threadIdx.x < 8) {
        float s = warpsum[threadIdx.x];
        #pragma unroll
        for (int o = 4; o; o >>= 1) s += __shfl_xor_sync(0xffu, s, o);
        if (threadIdx.x == 0) warpsum[0] = s;
    }
    __syncthreads();
    float inv = 1.0f / fmaxf(sqrtf(warpsum[0]), 1e-12f);
    float4 o4 = make_float4(f.x * inv, f.y * inv, f.z * inv, f.w * inv);
    reinterpret_cast<float4*>(g_norm + (size_t)row * D)[threadIdx.x] = o4;
    if (threadIdx.x == 0) g_maxenc[row] = enc_f(-2.0f);
}

// ---------------------------------------------------------------------------
// Kernel 2: tiled "GEMM" computing running row-max of G @ G^T (diag excluded).
// 128x128 tile per block, 256 threads, 8x8 per thread, f32x2 packed FMA.
// A smem tile stored as duplicated pairs (a,a) so inner loop needs no packing;
// B pairs (n, n+1) are naturally adjacent floats -> read as 8B values.
// ---------------------------------------------------------------------------
__global__ void __launch_bounds__(256, 2)
maxdot_kernel() {
    __shared__ ull   Asd[BK][BM];       // 16 KB, duplicated-pair A
    __shared__ float Bs[BK][BN];        //  8 KB

    const int i0 = blockIdx.y * BM;
    const int j0 = blockIdx.x * BN;
    const int tid = threadIdx.x;
    const int tx = tid & 15;            // column group
    const int ty = tid >> 4;            // row group

    ull acc[TM][TN / 2];
    #pragma unroll
    for (int m = 0; m < TM; m++)
        #pragma unroll
        for (int n = 0; n < TN / 2; n++) acc[m][n] = 0ull;

    for (int k0 = 0; k0 < D; k0 += BK) {
        // Cooperative tile load: 512 float4s per matrix, 2 per thread.
        #pragma unroll
        for (int r = 0; r < 2; r++) {
            int idx = tid + r * 256;        // 0..511
            int m   = idx >> 2;             // 0..127
            int kq  = (idx & 3) * 4;        // 0,4,8,12
            float4 a = *reinterpret_cast<const float4*>(
                &g_norm[(size_t)(i0 + m) * D + k0 + kq]);
            Asd[kq + 0][m] = pack2(a.x, a.x);
            Asd[kq + 1][m] = pack2(a.y, a.y);
            Asd[kq + 2][m] = pack2(a.z, a.z);
            Asd[kq + 3][m] = pack2(a.w, a.w);
            float4 b = *reinterpret_cast<const float4*>(
                &g_norm[(size_t)(j0 + m) * D + k0 + kq]);
            Bs[kq + 0][m] = b.x;
            Bs[kq + 1][m] = b.y;
            Bs[kq + 2][m] = b.z;
            Bs[kq + 3][m] = b.w;
        }
        __syncthreads();

        #pragma unroll
        for (int k = 0; k < BK; k++) {
            // 8 duplicated-pair A values (4x 16B loads)
            ull ap[TM];
            {
                const ulonglong2* arow =
                    reinterpret_cast<const ulonglong2*>(&Asd[k][ty * TM]);
                #pragma unroll
                for (int q = 0; q < 4; q++) {
                    ulonglong2 v = arow[q];
                    ap[2 * q + 0] = v.x;
                    ap[2 * q + 1] = v.y;
                }
            }
            // 4 natural B pairs (2x 16B loads)
            ull bp[TN / 2];
            {
                const ulonglong2* brow =
                    reinterpret_cast<const ulonglong2*>(&Bs[k][tx * TN]);
                ulonglong2 v0 = brow[0];
                ulonglong2 v1 = brow[1];
                bp[0] = v0.x; bp[1] = v0.y; bp[2] = v1.x; bp[3] = v1.y;
            }
            #pragma unroll
            for (int m = 0; m < TM; m++)
                #pragma unroll
                for (int n = 0; n < TN / 2; n++)
                    ffma2(acc[m][n], ap[m], bp[n]);
        }
        __syncthreads();
    }

    // Per-thread row max with diagonal exclusion
    float rmax[TM];
    #pragma unroll
    for (int m = 0; m < TM; m++) {
        int gi = i0 + ty * TM + m;
        float mx = -2.0f;
        #pragma unroll
        for (int n = 0; n < TN / 2; n++) {
            float lo, hi;
            unpack2(lo, hi, acc[m][n]);
            int gj = j0 + tx * TN + 2 * n;
            if (gi != gj)     mx = fmaxf(mx, lo);
            if (gi != gj + 1) mx = fmaxf(mx, hi);
        }
        rmax[m] = mx;
    }
    // Reduce across the 16 lanes sharing the same rows (tx dimension)
    #pragma unroll
    for (int o = 1; o < 16; o <<= 1)
        #pragma unroll
        for (int m = 0; m < TM; m++)
            rmax[m] = fmaxf(rmax[m], __shfl_xor_sync(0xffffffffu, rmax[m], o));
    if (tx == 0) {
        #pragma unroll
        for (int m = 0; m < TM; m++)
            atomicMax(&g_maxenc[i0 + ty * TM + m], enc_f(rmax[m]));
    }
}

// ---------------------------------------------------------------------------
// Kernel 3: loss = -mean(log(sqrt(2 - 2*maxdot) + eps))
// ---------------------------------------------------------------------------
__global__ void loss_kernel(float* __restrict__ out, int n) {
    float s = 0.0f;
    for (int i = threadIdx.x; i < n; i += blockDim.x) {
        float m  = dec_f(g_maxenc[i]);
        float d2 = fmaxf(2.0f - 2.0f * m, 0.0f);
        s += logf(sqrtf(d2) + 1e-8f);
    }
    #pragma unroll
    for (int o = 16; o; o >>= 1) s += __shfl_xor_sync(0xffffffffu, s, o);
    __shared__ float warpsum[8];
    if ((threadIdx.x & 31) == 0) warpsum[threadIdx.x >> 5] = s;
    __syncthreads();
    if (threadIdx.x == 0) {
        float t = 0.0f;
        #pragma unroll
        for (int w = 0; w < 8; w++) t += warpsum[w];
        out[0] = -t / (float)n;
    }
}

extern "C" void kernel_launch(void* const* d_in, const int* in_sizes, int n_in,
                              void* d_out, int out_size) {
    const float* feats = (const float*)d_in[0];
    int n = in_sizes[0] / D;   // 16384

    normalize_kernel<<<n, 256>>>(feats);
    dim3 grid(n / BN, n / BM);
    maxdot_kernel<<<grid, 256>>>();
    loss_kernel<<<1, 256>>>((float*)d_out, n);
}

// round 7
// speedup vs baseline: 22.9177x; 22.9177x over previous
#include <cuda_runtime.h>
#include <cuda_bf16.h>
#include <cstdint>

#define N_ROWS 16384
#define D 1024
#define TILE_M 128
#define TILE_N 128
#define BK 64                       // bf16 per k-stage (128 B rows)
#define KITERS (D / BK)             // 16
#define STAGE_BYTES 32768           // A tile 16 KB + B tile 16 KB
#define SM_TOTAL (2 * STAGE_BYTES)  // 64 KB dynamic smem

__device__ __nv_bfloat16 g_bf[(size_t)N_ROWS * D];
__device__ unsigned int  g_maxenc[N_ROWS];

// ---------- helpers ----------
__device__ __forceinline__ unsigned int enc_f(float f) {
    unsigned int u = __float_as_uint(f);
    return (u & 0x80000000u) ? ~u : (u | 0x80000000u);
}
__device__ __forceinline__ float dec_f(unsigned int e) {
    return (e & 0x80000000u) ? __uint_as_float(e & 0x7FFFFFFFu)
                             : __uint_as_float(~e);
}
__device__ __forceinline__ uint32_t smem_u32(const void* p) {
    uint32_t a;
    asm("{ .reg .u64 t; cvta.to.shared.u64 t, %1; cvt.u32.u64 %0, t; }" : "=r"(a) : "l"(p));
    return a;
}
#define SWZ128(o) ((o) ^ (((o) >> 3) & 0x70))

__device__ __forceinline__ void ldmatrix_x4(uint32_t& r0, uint32_t& r1,
                                            uint32_t& r2, uint32_t& r3,
                                            uint32_t addr) {
    asm volatile("ldmatrix.sync.aligned.m8n8.x4.shared.b16 {%0,%1,%2,%3}, [%4];"
                 : "=r"(r0), "=r"(r1), "=r"(r2), "=r"(r3) : "r"(addr));
}
__device__ __forceinline__ void mma16816(float& d0, float& d1, float& d2, float& d3,
                                         uint32_t a0, uint32_t a1, uint32_t a2, uint32_t a3,
                                         uint32_t b0, uint32_t b1) {
    asm volatile(
        "mma.sync.aligned.m16n8k16.row.col.f32.bf16.bf16.f32 "
        "{%0,%1,%2,%3}, {%4,%5,%6,%7}, {%8,%9}, {%0,%1,%2,%3};"
        : "+f"(d0), "+f"(d1), "+f"(d2), "+f"(d3)
        : "r"(a0), "r"(a1), "r"(a2), "r"(a3), "r"(b0), "r"(b1));
}

// ---------------------------------------------------------------------------
// Kernel 1: L2-normalize rows -> bf16; init per-row max accumulator.
// ---------------------------------------------------------------------------
__global__ void normalize_kernel(const float* __restrict__ feats) {
    int row = blockIdx.x;
    const float4* src = reinterpret_cast<const float4*>(feats + (size_t)row * D);
    float4 f = src[threadIdx.x];
    float ss = f.x*f.x + f.y*f.y + f.z*f.z + f.w*f.w;
    #pragma unroll
    for (int o = 16; o; o >>= 1) ss += __shfl_xor_sync(0xffffffffu, ss, o);
    __shared__ float warpsum[8];
    if ((threadIdx.x & 31) == 0) warpsum[threadIdx.x >> 5] = ss;
    __syncthreads();
    if (threadIdx.x < 8) {
        float s = warpsum[threadIdx.x];
        #pragma unroll
        for (int o = 4; o; o >>= 1) s += __shfl_xor_sync(0xffu, s, o);
        if (threadIdx.x == 0) warpsum[0] = s;
    }
    __syncthreads();
    float inv = 1.0f / fmaxf(sqrtf(warpsum[0]), 1e-12f);
    __nv_bfloat16* dst = g_bf + (size_t)row * D + threadIdx.x * 4;
    __nv_bfloat162 p0 = make_bfloat162(__float2bfloat16_rn(f.x*inv), __float2bfloat16_rn(f.y*inv));
    __nv_bfloat162 p1 = make_bfloat162(__float2bfloat16_rn(f.z*inv), __float2bfloat16_rn(f.w*inv));
    *reinterpret_cast<uint2*>(dst) = make_uint2(*reinterpret_cast<uint32_t*>(&p0),
                                                *reinterpret_cast<uint32_t*>(&p1));
    if (threadIdx.x == 0) g_maxenc[row] = enc_f(-2.0f);
}

// ---------------------------------------------------------------------------
// Kernel 2: HMMA bf16 Gram tile (128x128), lower triangle only; each tile
// feeds row-maxes (i side) AND column-maxes (j side) via symmetry.
// ---------------------------------------------------------------------------
__device__ __forceinline__ void load_stage(uint32_t sA, int i0, int j0,
                                           int kt, int tid) {
    // 128 rows x 8 chunks(16B) per matrix; 256 threads -> 4 chunks each.
    uint32_t sB = sA + 16384;
    #pragma unroll
    for (int q = 0; q < 4; q++) {
        int idx = tid + q * 256;
        int row = idx >> 3;
        int c   = idx & 7;
        uint32_t off = SWZ128((uint32_t)(row * 128 + c * 16));
        const void* srcA = (const void*)(g_bf + (size_t)(i0 + row) * D + kt * BK + c * 8);
        asm volatile("cp.async.cg.shared.global [%0], [%1], 16;" :: "r"(sA + off), "l"(srcA));
        const void* srcB = (const void*)(g_bf + (size_t)(j0 + row) * D + kt * BK + c * 8);
        asm volatile("cp.async.cg.shared.global [%0], [%1], 16;" :: "r"(sB + off), "l"(srcB));
    }
    asm volatile("cp.async.commit_group;");
}

__global__ void __launch_bounds__(256, 2) maxdot_mma_kernel() {
    int bx = blockIdx.x, by = blockIdx.y;
    if (by < bx) return;                 // symmetric: lower triangle only
    const int i0 = by * TILE_M;
    const int j0 = bx * TILE_N;

    extern __shared__ char smem[];
    __shared__ unsigned int red_r[128], red_c[128];
    uint32_t sb = smem_u32(smem);

    const int tid  = threadIdx.x;
    const int wid  = tid >> 5;
    const int lane = tid & 31;
    const int wm   = wid & 1;            // m offset 64*wm
    const int wn   = wid >> 1;           // n offset 32*wn

    if (tid < 128) red_r[tid] = enc_f(-2.0f);
    else           red_c[tid - 128] = enc_f(-2.0f);

    float acc[4][4][4];
    #pragma unroll
    for (int mi = 0; mi < 4; mi++)
        #pragma unroll
        for (int ni = 0; ni < 4; ni++)
            #pragma unroll
            for (int r = 0; r < 4; r++) acc[mi][ni][r] = 0.0f;

    // Per-thread ldmatrix row components
    const int aRow = (lane & 7) + ((lane >> 3) & 1) * 8;   // row within 16-row m-tile
    const int aKc  = (lane >> 4);                           // k-half chunk
    const int bRow = (lane & 7) + ((lane >> 4) & 1) * 8;   // row within 16 n-rows
    const int bKc  = ((lane >> 3) & 1);

    load_stage(sb, i0, j0, 0, tid);
    load_stage(sb + STAGE_BYTES, i0, j0, 1, tid);

    for (int kt = 0; kt < KITERS; kt++) {
        int s = kt & 1;
        asm volatile("cp.async.wait_group 1;" ::: "memory");
        __syncthreads();

        uint32_t aBase = sb + s * STAGE_BYTES;
        uint32_t bBase = aBase + 16384;
        #pragma unroll
        for (int ks = 0; ks < 4; ks++) {
            uint32_t a[4][4];
            #pragma unroll
            for (int mi = 0; mi < 4; mi++) {
                int row = wm * 64 + mi * 16 + aRow;
                int c   = ks * 2 + aKc;
                uint32_t off = SWZ128((uint32_t)(row * 128 + c * 16));
                ldmatrix_x4(a[mi][0], a[mi][1], a[mi][2], a[mi][3], aBase + off);
            }
            uint32_t b[4][2];
            #pragma unroll
            for (int nb = 0; nb < 2; nb++) {
                int row = wn * 32 + nb * 16 + bRow;
                int c   = ks * 2 + bKc;
                uint32_t off = SWZ128((uint32_t)(row * 128 + c * 16));
                ldmatrix_x4(b[2*nb][0], b[2*nb][1], b[2*nb+1][0], b[2*nb+1][1],
                            bBase + off);
            }
            #pragma unroll
            for (int mi = 0; mi < 4; mi++)
                #pragma unroll
                for (int ni = 0; ni < 4; ni++)
                    mma16816(acc[mi][ni][0], acc[mi][ni][1],
                             acc[mi][ni][2], acc[mi][ni][3],
                             a[mi][0], a[mi][1], a[mi][2], a[mi][3],
                             b[ni][0], b[ni][1]);
        }
        __syncthreads();
        if (kt + 2 < KITERS)
            load_stage(sb + s * STAGE_BYTES, i0, j0, kt + 2, tid);
    }

    // Diagonal exclusion (diagonal tiles only)
    if (i0 == j0) {
        #pragma unroll
        for (int mi = 0; mi < 4; mi++)
            #pragma unroll
            for (int ni = 0; ni < 4; ni++)
                #pragma unroll
                for (int r = 0; r < 4; r++) {
                    int rl = wm * 64 + mi * 16 + (lane >> 2) + (r >> 1) * 8;
                    int cl = wn * 32 + ni * 8 + (lane & 3) * 2 + (r & 1);
                    if (rl == cl) acc[mi][ni][r] = -2.0f;
                }
    }

    // Row-max: reduce over ni + col pairs in-thread, then lanes sharing row
    #pragma unroll
    for (int mi = 0; mi < 4; mi++) {
        #pragma unroll
        for (int h = 0; h < 2; h++) {
            float v = -2.0f;
            #pragma unroll
            for (int ni = 0; ni < 4; ni++) {
                v = fmaxf(v, acc[mi][ni][h * 2 + 0]);
                v = fmaxf(v, acc[mi][ni][h * 2 + 1]);
            }
            v = fmaxf(v, __shfl_xor_sync(0xffffffffu, v, 1));
            v = fmaxf(v, __shfl_xor_sync(0xffffffffu, v, 2));
            if ((lane & 3) == 0) {
                int rl = wm * 64 + mi * 16 + (lane >> 2) + h * 8;
                atomicMax(&red_r[rl], enc_f(v));
            }
        }
    }
    // Col-max: reduce over mi + row halves in-thread, then lanes sharing col
    #pragma unroll
    for (int ni = 0; ni < 4; ni++) {
        #pragma unroll
        for (int j = 0; j < 2; j++) {
            float v = -2.0f;
            #pragma unroll
            for (int mi = 0; mi < 4; mi++) {
                v = fmaxf(v, acc[mi][ni][j]);
                v = fmaxf(v, acc[mi][ni][2 + j]);
            }
            v = fmaxf(v, __shfl_xor_sync(0xffffffffu, v, 4));
            v = fmaxf(v, __shfl_xor_sync(0xffffffffu, v, 8));
            v = fmaxf(v, __shfl_xor_sync(0xffffffffu, v, 16));
            if ((lane >> 2) == 0) {
                int cl = wn * 32 + ni * 8 + (lane & 3) * 2 + j;
                atomicMax(&red_c[cl], enc_f(v));
            }
        }
    }
    __syncthreads();

    if (tid < 128) {
        atomicMax(&g_maxenc[i0 + tid], red_r[tid]);
    } else if (i0 != j0) {
        atomicMax(&g_maxenc[j0 + tid - 128], red_c[tid - 128]);
    }
}

// ---------------------------------------------------------------------------
// Kernel 3: loss = -mean(log(sqrt(2 - 2*maxdot) + eps))
// ---------------------------------------------------------------------------
__global__ void loss_kernel(float* __restrict__ out, int n) {
    float s = 0.0f;
    for (int i = threadIdx.x; i < n; i += blockDim.x) {
        float m  = dec_f(g_maxenc[i]);
        float d2 = fmaxf(2.0f - 2.0f * m, 0.0f);
        s += logf(sqrtf(d2) + 1e-8f);
    }
    #pragma unroll
    for (int o = 16; o; o >>= 1) s += __shfl_xor_sync(0xffffffffu, s, o);
    __shared__ float warpsum[8];
    if ((threadIdx.x & 31) == 0) warpsum[threadIdx.x >> 5] = s;
    __syncthreads();
    if (threadIdx.x == 0) {
        float t = 0.0f;
        #pragma unroll
        for (int w = 0; w < 8; w++) t += warpsum[w];
        out[0] = -t / (float)n;
    }
}

extern "C" void kernel_launch(void* const* d_in, const int* in_sizes, int n_in,
                              void* d_out, int out_size) {
    const float* feats = (const float*)d_in[0];
    int n = in_sizes[0] / D;   // 16384

    cudaFuncSetAttribute(maxdot_mma_kernel,
                         cudaFuncAttributeMaxDynamicSharedMemorySize, SM_TOTAL);

    normalize_kernel<<<n, 256>>>(feats);
    dim3 grid(N_ROWS / TILE_N, N_ROWS / TILE_M);
    maxdot_mma_kernel<<<grid, 256, SM_TOTAL>>>();
    loss_kernel<<<1, 256>>>((float*)d_out, n);
}